// round 9
// baseline (speedup 1.0000x reference)
#include <cuda_runtime.h>
#include <math.h>
#include <stdint.h>

// Problem dims (fixed by the dataset)
#define Bq   64      // batch
#define Nn   2048    // nodes
#define DIN  2
#define Hh   64      // hidden = O
#define Dd   16      // embed dim
#define Cc   66      // DIN + Hh
#define Oo   64
#define BC   4224    // Bq*Cc
#define WSZ  8448    // 2*Cc*Oo

typedef unsigned long long u64;

// Packed f32x2 FMA (sm_103a FFMA2) — two independent fp32 FMAs, bit-identical
// to scalar FFMA per lane. Only reachable via PTX (ptxas never auto-fuses).
#define FMA_F32X2(d, a, b, c) \
    asm("fma.rn.f32x2 %0, %1, %2, %3;" : "=l"(d) : "l"(a), "l"(b), "l"(c))
#define PACK_DUP_F32X2(d, v) \
    asm("mov.b64 %0, {%1, %1};" : "=l"(d) : "r"(__float_as_uint(v)))

// ---------------- scratch (device globals; no allocations) ----------------
__device__ float g_e [3][Nn * Dd];        // per-gate layernormed embeddings
__device__ float g_A [3][Nn * Nn];        // per-gate adjacency (softmax)
__device__ float g_Xt[Nn * BC];           // xs  transposed to [m][b*C+c]
__device__ float g_Ct[Nn * BC];           // cand transposed
__device__ float g_G [2][Nn * BC];        // A @ X results
__device__ float g_Wn[3][Nn * WSZ];       // per-node adaptive weights e[n]@W_pool
__device__ float g_z [Bq * Nn * Hh];
__device__ float g_r [Bq * Nn * Hh];

// FFMA-only exp (no MUFU): exp(x) = 2^(x*log2e), poly on [-0.5,0.5].
// |rel err| ~1e-7. Input clamped to avoid exponent over/underflow.
__device__ __forceinline__ float fast_exp(float x)
{
    float y = x * 1.442695041f;
    y = fminf(fmaxf(y, -125.0f), 125.0f);
    int   ni = __float2int_rn(y);
    float f  = y - (float)ni;
    float p = 1.339077600e-3f;
    p = fmaf(p, f, 9.618012930e-3f);
    p = fmaf(p, f, 5.550487860e-2f);
    p = fmaf(p, f, 2.402264923e-1f);
    p = fmaf(p, f, 6.931471825e-1f);
    p = fmaf(p, f, 1.0f);
    float s = __int_as_float((ni + 127) << 23);
    return p * s;
}

__device__ __forceinline__ float fast_sigmoid(float x)
{
    return 1.0f / (1.0f + fast_exp(-x));
}

__device__ __forceinline__ float fast_tanh(float x)
{
    float xc = fminf(fmaxf(x, -15.0f), 15.0f);
    return 1.0f - 2.0f / (fast_exp(2.0f * xc) + 1.0f);
}

// ---------------- 1) layernorm embeddings ----------------
__global__ void compute_e_kernel(const float* __restrict__ ne, const float* __restrict__ te,
                                 const float* __restrict__ gz, const float* __restrict__ bz,
                                 const float* __restrict__ gr, const float* __restrict__ br,
                                 const float* __restrict__ gu, const float* __restrict__ bu)
{
    int idx = blockIdx.x * blockDim.x + threadIdx.x;
    if (idx >= 3 * Nn) return;
    int g = idx / Nn, n = idx - g * Nn;
    const float* ga = (g == 0) ? gz : (g == 1) ? gr : gu;
    const float* be = (g == 0) ? bz : (g == 1) ? br : bu;

    float v[Dd];
    float m = 0.f;
    #pragma unroll
    for (int d = 0; d < Dd; d++) { v[d] = ne[n * Dd + d] + te[d]; m += v[d]; }
    m *= (1.f / Dd);
    float var = 0.f;
    #pragma unroll
    for (int d = 0; d < Dd; d++) { float t = v[d] - m; var += t * t; }
    var *= (1.f / Dd);
    float rs = rsqrtf(var + 1e-12f);
    #pragma unroll
    for (int d = 0; d < Dd; d++)
        g_e[g][n * Dd + d] = (v[d] - m) * rs * ga[d] + be[d];
}

// ---------------- 2) A = softmax(e e^T) rows; 4 rows per block ----------------
__global__ __launch_bounds__(256) void softmax_kernel()
{
    int g  = blockIdx.y;
    int n0 = blockIdx.x * 4;
    __shared__ float rows[4][Nn];          // 32 KB
    __shared__ float en[4][Dd];
    __shared__ float red[4][8];
    int t = threadIdx.x;

    if (t < 64) en[t >> 4][t & 15] = g_e[g][(n0 + (t >> 4)) * Dd + (t & 15)];
    __syncthreads();

    float lmax[4] = {-1e30f, -1e30f, -1e30f, -1e30f};
    for (int m = t; m < Nn; m += 256) {
        float ev[Dd];
        #pragma unroll
        for (int d = 0; d < Dd; d++) ev[d] = g_e[g][m * Dd + d];
        #pragma unroll
        for (int r = 0; r < 4; r++) {
            float s = 0.f;
            #pragma unroll
            for (int d = 0; d < Dd; d++) s += ev[d] * en[r][d];
            rows[r][m] = s;
            lmax[r] = fmaxf(lmax[r], s);
        }
    }
    #pragma unroll
    for (int r = 0; r < 4; r++) {
        float v = lmax[r];
        #pragma unroll
        for (int off = 16; off; off >>= 1) v = fmaxf(v, __shfl_xor_sync(0xffffffffu, v, off));
        if ((t & 31) == 0) red[r][t >> 5] = v;
    }
    __syncthreads();
    float bmax[4];
    #pragma unroll
    for (int r = 0; r < 4; r++) {
        float v = red[r][0];
        #pragma unroll
        for (int w = 1; w < 8; w++) v = fmaxf(v, red[r][w]);
        bmax[r] = v;
    }
    __syncthreads();

    float lsum[4] = {0.f, 0.f, 0.f, 0.f};
    for (int m = t; m < Nn; m += 256) {
        #pragma unroll
        for (int r = 0; r < 4; r++) {
            float ev = fast_exp(rows[r][m] - bmax[r]);
            rows[r][m] = ev;
            lsum[r] += ev;
        }
    }
    #pragma unroll
    for (int r = 0; r < 4; r++) {
        float v = lsum[r];
        #pragma unroll
        for (int off = 16; off; off >>= 1) v += __shfl_xor_sync(0xffffffffu, v, off);
        if ((t & 31) == 0) red[r][t >> 5] = v;
    }
    __syncthreads();
    float inv[4];
    #pragma unroll
    for (int r = 0; r < 4; r++) {
        float v = 0.f;
        #pragma unroll
        for (int w = 0; w < 8; w++) v += red[r][w];
        inv[r] = 1.f / v;
    }
    for (int m = t; m < Nn; m += 256) {
        #pragma unroll
        for (int r = 0; r < 4; r++)
            g_A[g][(size_t)(n0 + r) * Nn + m] = rows[r][m] * inv[r];
    }
}

// ---------------- 3) transposes into [m][b*C+c] ----------------
__global__ void build_xt_kernel(const float* __restrict__ x, const float* __restrict__ state)
{
    int idx = blockIdx.x * blockDim.x + threadIdx.x;
    if (idx >= Nn * BC) return;
    int m = idx / BC;
    int j = idx - m * BC;
    int b = j / Cc;
    int c = j - b * Cc;
    float v;
    if (c < DIN) v = x[((size_t)b * Nn + m) * DIN + c];
    else         v = state[((size_t)b * Nn + m) * Hh + (c - DIN)];
    g_Xt[idx] = v;
}

__global__ void build_ct_kernel(const float* __restrict__ x, const float* __restrict__ state)
{
    int idx = blockIdx.x * blockDim.x + threadIdx.x;
    if (idx >= Nn * BC) return;
    int m = idx / BC;
    int j = idx - m * BC;
    int b = j / Cc;
    int c = j - b * Cc;
    float v;
    if (c < DIN) v = x[((size_t)b * Nn + m) * DIN + c];
    else {
        size_t o = ((size_t)b * Nn + m) * Hh + (c - DIN);
        v = g_z[o] * state[o];
    }
    g_Ct[idx] = v;
}

// ---------------- 4) Wn_all[g][n][j] = sum_d e[g][n][d] * W_pool[d][j] ----------------
// grid: (WSZ/128 = 66, Nn/128 = 16, 3)
__global__ __launch_bounds__(256) void wn_kernel(const float* __restrict__ Wz,
                                                 const float* __restrict__ Wr,
                                                 const float* __restrict__ Wu)
{
    int gate = blockIdx.z;
    const float* Wp = (gate == 0) ? Wz : (gate == 1) ? Wr : Wu;
    int j0 = blockIdx.x * 128;
    int n0 = blockIdx.y * 128;
    __shared__ __align__(16) float sE[128][Dd];   // 8 KB
    __shared__ __align__(16) float sW[Dd][128];   // 8 KB
    int t = threadIdx.x;

    #pragma unroll
    for (int q = 0; q < 2; q++) {
        int id  = q * 256 + t;
        int rr  = id >> 2, c4 = id & 3;
        *(float4*)&sE[rr][c4 * 4] = *(const float4*)&g_e[gate][(n0 + rr) * Dd + c4 * 4];
        int wr  = id >> 5, wc4 = id & 31;
        *(float4*)&sW[wr][wc4 * 4] = *(const float4*)&Wp[(size_t)wr * WSZ + j0 + wc4 * 4];
    }
    __syncthreads();

    int jl  = (t & 31) * 4;
    int nl0 = (t >> 5) * 16;
    float acc[16][4] = {};
    #pragma unroll
    for (int d = 0; d < Dd; d++) {
        float4 wv = *(float4*)&sW[d][jl];
        #pragma unroll
        for (int r = 0; r < 16; r++) {
            float ev = sE[nl0 + r][d];
            acc[r][0] += ev * wv.x;
            acc[r][1] += ev * wv.y;
            acc[r][2] += ev * wv.z;
            acc[r][3] += ev * wv.w;
        }
    }
    #pragma unroll
    for (int r = 0; r < 16; r++) {
        float4 v = make_float4(acc[r][0], acc[r][1], acc[r][2], acc[r][3]);
        *(float4*)&g_Wn[gate][(size_t)(n0 + nl0 + r) * WSZ + j0 + jl] = v;
    }
}

// ---------------- 5) main SGEMM: G = A @ X  (M=2048, K=2048, Ncol=4224) ----------------
// 128x128x16 tiles, 256 threads, 8x8 per thread, double-buffered smem.
// Inner loop uses packed fma.rn.f32x2 (FFMA2): 32 packed FMAs replace 64 FFMA,
// halving fma-pipe pressure; bit-identical results per lane.
// grid: (33, 16, nz); A = g_A[gateOff + z], X = useCt ? g_Ct : g_Xt, G = g_G[outOff + z]
#define AS_PAD 132   // 128 + 4: kills 4-way bank conflicts on transposed As stores
__global__ __launch_bounds__(256, 2) void sgemm_kernel(int gateOff, int useCt, int outOff)
{
    const float* A = g_A[gateOff + blockIdx.z];
    const float* X = useCt ? g_Ct : g_Xt;
    float*       G = g_G[outOff + blockIdx.z];

    int j0 = blockIdx.x * 128;
    int r0 = blockIdx.y * 128;

    __shared__ __align__(16) float As[2][16][AS_PAD];
    __shared__ __align__(16) float Bs[2][16][128];

    int t  = threadIdx.x;
    int tx = t & 15, ty = t >> 4;

    u64 acc2[8][4] = {};   // 8 rows x 4 packed column-pairs (low lane = even col)
    float4 pa[2], pb[2];

    // initial tile (k0 = 0)
    #pragma unroll
    for (int q = 0; q < 2; q++) {
        int id  = q * 256 + t;
        int ar  = id >> 2, ac4 = id & 3;
        float4 v = *(const float4*)&A[(size_t)(r0 + ar) * Nn + ac4 * 4];
        As[0][ac4 * 4 + 0][ar] = v.x;
        As[0][ac4 * 4 + 1][ar] = v.y;
        As[0][ac4 * 4 + 2][ar] = v.z;
        As[0][ac4 * 4 + 3][ar] = v.w;
        int xr = id >> 5, xc4 = id & 31;
        *(float4*)&Bs[0][xr][xc4 * 4] = *(const float4*)&X[(size_t)xr * BC + j0 + xc4 * 4];
    }
    __syncthreads();

    const int KT = Nn / 16;   // 128
    for (int kt = 0; kt < KT; kt++) {
        int cur = kt & 1, nxt = cur ^ 1;
        int k0n = (kt + 1) * 16;
        if (kt + 1 < KT) {
            #pragma unroll
            for (int q = 0; q < 2; q++) {
                int id  = q * 256 + t;
                int ar  = id >> 2, ac4 = id & 3;
                pa[q] = *(const float4*)&A[(size_t)(r0 + ar) * Nn + k0n + ac4 * 4];
                int xr = id >> 5, xc4 = id & 31;
                pb[q] = *(const float4*)&X[(size_t)(k0n + xr) * BC + j0 + xc4 * 4];
            }
        }
        #pragma unroll
        for (int kk = 0; kk < 16; kk++) {
            float4 a0 = *(float4*)&As[cur][kk][ty * 8];
            float4 a1 = *(float4*)&As[cur][kk][ty * 8 + 4];
            // B columns as packed f32x2 pairs (16B-aligned: tx*8 floats = 32B)
            ulonglong2 q0 = *(ulonglong2*)&Bs[cur][kk][tx * 8];
            ulonglong2 q1 = *(ulonglong2*)&Bs[cur][kk][tx * 8 + 4];
            float av[8] = {a0.x, a0.y, a0.z, a0.w, a1.x, a1.y, a1.z, a1.w};
            #pragma unroll
            for (int i = 0; i < 8; i++) {
                u64 ad;
                PACK_DUP_F32X2(ad, av[i]);
                FMA_F32X2(acc2[i][0], ad, q0.x, acc2[i][0]);
                FMA_F32X2(acc2[i][1], ad, q0.y, acc2[i][1]);
                FMA_F32X2(acc2[i][2], ad, q1.x, acc2[i][2]);
                FMA_F32X2(acc2[i][3], ad, q1.y, acc2[i][3]);
            }
        }
        if (kt + 1 < KT) {
            #pragma unroll
            for (int q = 0; q < 2; q++) {
                int id  = q * 256 + t;
                int ar  = id >> 2, ac4 = id & 3;
                As[nxt][ac4 * 4 + 0][ar] = pa[q].x;
                As[nxt][ac4 * 4 + 1][ar] = pa[q].y;
                As[nxt][ac4 * 4 + 2][ar] = pa[q].z;
                As[nxt][ac4 * 4 + 3][ar] = pa[q].w;
                int xr = id >> 5, xc4 = id & 31;
                *(float4*)&Bs[nxt][xr][xc4 * 4] = pb[q];
            }
        }
        __syncthreads();
    }

    #pragma unroll
    for (int i = 0; i < 8; i++) {
        size_t rowo = (size_t)(r0 + ty * 8 + i) * BC + j0 + tx * 8;
        float2 c0 = *(float2*)&acc2[i][0];
        float2 c1 = *(float2*)&acc2[i][1];
        float2 c2 = *(float2*)&acc2[i][2];
        float2 c3 = *(float2*)&acc2[i][3];
        *(float4*)&G[rowo]     = make_float4(c0.x, c0.y, c1.x, c1.y);
        *(float4*)&G[rowo + 4] = make_float4(c2.x, c2.y, c3.x, c3.y);
    }
}

// ---------------- 6) per-node combine + activation (+ final GRU fuse for gate u) ----------
// out[b,n,o] = act( sum_i X[n,b,i]*Wn[n,0,i,o] + sum_i G[n,b,i]*Wn[n,1,i,o] + bias[n,o] )
// block per n; 256 threads = 16x16; each thread a 4x4 (b x o) tile over K=132 in 2 passes.
__global__ __launch_bounds__(256) void combine_kernel(const float* __restrict__ b_pool,
                                                      const float* __restrict__ state,
                                                      float* __restrict__ dout,
                                                      int gate, int useCt, int gsel, int outMode)
{
    __shared__ __align__(16) float sW[Cc * Oo];        // 16.9 KB : one support's weights [k][o]
    __shared__ __align__(16) float sXT[Cc][68];        // 17.9 KB : X chunk transposed [c][b]
    __shared__ float sBias[Oo];
    __shared__ float se[Dd];

    int n = blockIdx.x, t = threadIdx.x;
    if (t < Dd) se[t] = g_e[gate][n * Dd + t];
    __syncthreads();
    if (t < Oo) {
        float a = 0.f;
        #pragma unroll
        for (int d = 0; d < Dd; d++) a += se[d] * b_pool[d * Oo + t];
        sBias[t] = a;
    }

    int tx = t & 15, ty = t >> 4;
    float acc[4][4] = {};
    const float* Wn = &g_Wn[gate][(size_t)n * WSZ];

    #pragma unroll
    for (int pass = 0; pass < 2; pass++) {
        const float* xs = pass ? &g_G[gsel][(size_t)n * BC]
                               : (useCt ? &g_Ct[(size_t)n * BC] : &g_Xt[(size_t)n * BC]);
        const float4* wsrc = (const float4*)(Wn + pass * (Cc * Oo));
        for (int i4 = t; i4 < (Cc * Oo) / 4; i4 += 256)
            ((float4*)sW)[i4] = wsrc[i4];
        for (int idx = t; idx < BC; idx += 256) {
            int b = idx / Cc, c = idx - b * Cc;
            sXT[c][b] = xs[idx];
        }
        __syncthreads();
        #pragma unroll
        for (int k = 0; k < Cc; k++) {
            float4 bv = *(float4*)&sW[k * Oo + tx * 4];
            float4 av = *(float4*)&sXT[k][ty * 4];
            float aa[4] = {av.x, av.y, av.z, av.w};
            float bb[4] = {bv.x, bv.y, bv.z, bv.w};
            #pragma unroll
            for (int i = 0; i < 4; i++)
                #pragma unroll
                for (int j = 0; j < 4; j++)
                    acc[i][j] += aa[i] * bb[j];
        }
        __syncthreads();
    }

    #pragma unroll
    for (int bi = 0; bi < 4; bi++) {
        int b = ty * 4 + bi;
        size_t base = ((size_t)b * Nn + n) * Hh + tx * 4;
        float4 v;
        if (outMode == 2) {
            float4 rv = *(const float4*)&g_r[base];
            float4 sv = *(const float4*)&state[base];
            float h0 = fast_tanh(acc[bi][0] + sBias[tx * 4 + 0]);
            float h1 = fast_tanh(acc[bi][1] + sBias[tx * 4 + 1]);
            float h2 = fast_tanh(acc[bi][2] + sBias[tx * 4 + 2]);
            float h3 = fast_tanh(acc[bi][3] + sBias[tx * 4 + 3]);
            v.x = rv.x * sv.x + (1.f - rv.x) * h0;
            v.y = rv.y * sv.y + (1.f - rv.y) * h1;
            v.z = rv.z * sv.z + (1.f - rv.z) * h2;
            v.w = rv.w * sv.w + (1.f - rv.w) * h3;
            *(float4*)&dout[base] = v;
        } else {
            v.x = fast_sigmoid(acc[bi][0] + sBias[tx * 4 + 0]);
            v.y = fast_sigmoid(acc[bi][1] + sBias[tx * 4 + 1]);
            v.z = fast_sigmoid(acc[bi][2] + sBias[tx * 4 + 2]);
            v.w = fast_sigmoid(acc[bi][3] + sBias[tx * 4 + 3]);
            float* outp = (outMode == 0) ? g_z : g_r;
            *(float4*)&outp[base] = v;
        }
    }
}

// ---------------- launcher ----------------
extern "C" void kernel_launch(void* const* d_in, const int* in_sizes, int n_in,
                              void* d_out, int out_size)
{
    (void)in_sizes; (void)n_in; (void)out_size;
    const float* x   = (const float*)d_in[0];
    const float* st  = (const float*)d_in[1];
    const float* ne  = (const float*)d_in[2];
    const float* te  = (const float*)d_in[3];
    const float* Wz  = (const float*)d_in[4];
    const float* bz  = (const float*)d_in[5];
    const float* gz  = (const float*)d_in[6];
    const float* bez = (const float*)d_in[7];
    const float* Wr  = (const float*)d_in[8];
    const float* brr = (const float*)d_in[9];
    const float* gr  = (const float*)d_in[10];
    const float* ber = (const float*)d_in[11];
    const float* Wu  = (const float*)d_in[12];
    const float* bu  = (const float*)d_in[13];
    const float* gu  = (const float*)d_in[14];
    const float* beu = (const float*)d_in[15];
    float* out = (float*)d_out;

    compute_e_kernel<<<(3 * Nn + 255) / 256, 256>>>(ne, te, gz, bez, gr, ber, gu, beu);
    softmax_kernel<<<dim3(Nn / 4, 3), 256>>>();
    build_xt_kernel<<<(Nn * BC + 255) / 256, 256>>>(x, st);
    wn_kernel<<<dim3(WSZ / 128, Nn / 128, 3), 256>>>(Wz, Wr, Wu);

    // z and r big GEMMs batched (z in gridDim.z)
    sgemm_kernel<<<dim3(BC / 128, Nn / 128, 2), 256>>>(0, 0, 0);
    combine_kernel<<<Nn, 256>>>(bz, st, out, 0, 0, 0, 0);   // -> g_z
    combine_kernel<<<Nn, 256>>>(brr, st, out, 1, 0, 1, 1);  // -> g_r

    build_ct_kernel<<<(Nn * BC + 255) / 256, 256>>>(x, st); // cand = [x, z*state]
    sgemm_kernel<<<dim3(BC / 128, Nn / 128, 1), 256>>>(2, 1, 0);
    combine_kernel<<<Nn, 256>>>(bu, st, out, 2, 1, 0, 2);   // -> d_out (GRU fuse)
}

// round 10
// speedup vs baseline: 2.0356x; 2.0356x over previous
#include <cuda_runtime.h>
#include <cuda_bf16.h>
#include <math.h>
#include <stdint.h>

// Problem dims (fixed by the dataset)
#define Bq   64      // batch
#define Nn   2048    // nodes
#define DIN  2
#define Hh   64      // hidden = O
#define Dd   16      // embed dim
#define Cc   66      // DIN + Hh
#define Oo   64
#define BC   4224    // Bq*Cc
#define WSZ  8448    // 2*Cc*Oo

// ---------------- scratch (device globals; no allocations) ----------------
__device__ float g_e [3][Nn * Dd];            // per-gate layernormed embeddings
__device__ __nv_bfloat16 g_Ah[3][Nn * Nn];    // adjacency hi (bf16)
__device__ __nv_bfloat16 g_Al[3][Nn * Nn];    // adjacency lo (residual bf16)
__device__ float g_Xt[Nn * BC];               // xs  transposed [m][b*C+c] fp32 (combine pass0)
__device__ float g_Ct[Nn * BC];               // cand transposed fp32
__device__ __nv_bfloat16 g_Xh[Nn * BC];       // X hi (bf16)  — reused for cand
__device__ __nv_bfloat16 g_Xl[Nn * BC];       // X lo
__device__ float g_G [2][Nn * BC];            // A @ X results (fp32)
__device__ float g_Wn[3][Nn * WSZ];           // per-node adaptive weights e[n]@W_pool
__device__ float g_z [Bq * Nn * Hh];
__device__ float g_r [Bq * Nn * Hh];

// ---------------- PTX helpers ----------------
#define LDSM_X4(d, addr) \
    asm volatile("ldmatrix.sync.aligned.m8n8.x4.shared.b16 {%0,%1,%2,%3}, [%4];" \
        : "=r"(d[0]), "=r"(d[1]), "=r"(d[2]), "=r"(d[3]) : "r"(addr))
#define LDSM_X4_T(d, addr) \
    asm volatile("ldmatrix.sync.aligned.m8n8.x4.trans.shared.b16 {%0,%1,%2,%3}, [%4];" \
        : "=r"(d[0]), "=r"(d[1]), "=r"(d[2]), "=r"(d[3]) : "r"(addr))
#define MMA_BF16(c, a, b0, b1) \
    asm volatile("mma.sync.aligned.m16n8k16.row.col.f32.bf16.bf16.f32 " \
        "{%0,%1,%2,%3}, {%4,%5,%6,%7}, {%8,%9}, {%0,%1,%2,%3};" \
        : "+f"(c[0]), "+f"(c[1]), "+f"(c[2]), "+f"(c[3]) \
        : "r"(a[0]), "r"(a[1]), "r"(a[2]), "r"(a[3]), "r"(b0), "r"(b1))
#define CP_ASYNC16(smem_u32, gptr) \
    asm volatile("cp.async.cg.shared.global [%0], [%1], 16;" :: "r"(smem_u32), "l"(gptr))
#define CP_COMMIT() asm volatile("cp.async.commit_group;" ::: "memory")
#define CP_WAIT0()  asm volatile("cp.async.wait_group 0;" ::: "memory")

__device__ __forceinline__ void split_bf16(float v, __nv_bfloat16& h, __nv_bfloat16& l)
{
    h = __float2bfloat16(v);
    l = __float2bfloat16(v - __bfloat162float(h));
}

// FFMA-only exp (no MUFU)
__device__ __forceinline__ float fast_exp(float x)
{
    float y = x * 1.442695041f;
    y = fminf(fmaxf(y, -125.0f), 125.0f);
    int   ni = __float2int_rn(y);
    float f  = y - (float)ni;
    float p = 1.339077600e-3f;
    p = fmaf(p, f, 9.618012930e-3f);
    p = fmaf(p, f, 5.550487860e-2f);
    p = fmaf(p, f, 2.402264923e-1f);
    p = fmaf(p, f, 6.931471825e-1f);
    p = fmaf(p, f, 1.0f);
    float s = __int_as_float((ni + 127) << 23);
    return p * s;
}
__device__ __forceinline__ float fast_sigmoid(float x) { return 1.0f / (1.0f + fast_exp(-x)); }
__device__ __forceinline__ float fast_tanh(float x)
{
    float xc = fminf(fmaxf(x, -15.0f), 15.0f);
    return 1.0f - 2.0f / (fast_exp(2.0f * xc) + 1.0f);
}

// ---------------- 1) layernorm embeddings ----------------
__global__ void compute_e_kernel(const float* __restrict__ ne, const float* __restrict__ te,
                                 const float* __restrict__ gz, const float* __restrict__ bz,
                                 const float* __restrict__ gr, const float* __restrict__ br,
                                 const float* __restrict__ gu, const float* __restrict__ bu)
{
    int idx = blockIdx.x * blockDim.x + threadIdx.x;
    if (idx >= 3 * Nn) return;
    int g = idx / Nn, n = idx - g * Nn;
    const float* ga = (g == 0) ? gz : (g == 1) ? gr : gu;
    const float* be = (g == 0) ? bz : (g == 1) ? br : bu;

    float v[Dd];
    float m = 0.f;
    #pragma unroll
    for (int d = 0; d < Dd; d++) { v[d] = ne[n * Dd + d] + te[d]; m += v[d]; }
    m *= (1.f / Dd);
    float var = 0.f;
    #pragma unroll
    for (int d = 0; d < Dd; d++) { float t = v[d] - m; var += t * t; }
    var *= (1.f / Dd);
    float rs = rsqrtf(var + 1e-12f);
    #pragma unroll
    for (int d = 0; d < Dd; d++)
        g_e[g][n * Dd + d] = (v[d] - m) * rs * ga[d] + be[d];
}

// ---------------- 2) A = softmax(e e^T); writes bf16 hi/lo directly ----------------
__global__ __launch_bounds__(256) void softmax_kernel()
{
    int g  = blockIdx.y;
    int n0 = blockIdx.x * 4;
    __shared__ float rows[4][Nn];
    __shared__ float en[4][Dd];
    __shared__ float red[4][8];
    int t = threadIdx.x;

    if (t < 64) en[t >> 4][t & 15] = g_e[g][(n0 + (t >> 4)) * Dd + (t & 15)];
    __syncthreads();

    float lmax[4] = {-1e30f, -1e30f, -1e30f, -1e30f};
    for (int m = t; m < Nn; m += 256) {
        float ev[Dd];
        #pragma unroll
        for (int d = 0; d < Dd; d++) ev[d] = g_e[g][m * Dd + d];
        #pragma unroll
        for (int r = 0; r < 4; r++) {
            float s = 0.f;
            #pragma unroll
            for (int d = 0; d < Dd; d++) s += ev[d] * en[r][d];
            rows[r][m] = s;
            lmax[r] = fmaxf(lmax[r], s);
        }
    }
    #pragma unroll
    for (int r = 0; r < 4; r++) {
        float v = lmax[r];
        #pragma unroll
        for (int off = 16; off; off >>= 1) v = fmaxf(v, __shfl_xor_sync(0xffffffffu, v, off));
        if ((t & 31) == 0) red[r][t >> 5] = v;
    }
    __syncthreads();
    float bmax[4];
    #pragma unroll
    for (int r = 0; r < 4; r++) {
        float v = red[r][0];
        #pragma unroll
        for (int w = 1; w < 8; w++) v = fmaxf(v, red[r][w]);
        bmax[r] = v;
    }
    __syncthreads();

    float lsum[4] = {0.f, 0.f, 0.f, 0.f};
    for (int m = t; m < Nn; m += 256) {
        #pragma unroll
        for (int r = 0; r < 4; r++) {
            float ev = fast_exp(rows[r][m] - bmax[r]);
            rows[r][m] = ev;
            lsum[r] += ev;
        }
    }
    #pragma unroll
    for (int r = 0; r < 4; r++) {
        float v = lsum[r];
        #pragma unroll
        for (int off = 16; off; off >>= 1) v += __shfl_xor_sync(0xffffffffu, v, off);
        if ((t & 31) == 0) red[r][t >> 5] = v;
    }
    __syncthreads();
    float inv[4];
    #pragma unroll
    for (int r = 0; r < 4; r++) {
        float v = 0.f;
        #pragma unroll
        for (int w = 0; w < 8; w++) v += red[r][w];
        inv[r] = 1.f / v;
    }
    for (int m = t; m < Nn; m += 256) {
        #pragma unroll
        for (int r = 0; r < 4; r++) {
            float v = rows[r][m] * inv[r];
            size_t idx = (size_t)(n0 + r) * Nn + m;
            __nv_bfloat16 h, l;
            split_bf16(v, h, l);
            g_Ah[g][idx] = h;
            g_Al[g][idx] = l;
        }
    }
}

// ---------------- 3) transposes: fp32 + bf16 hi/lo ----------------
__global__ void build_xt_kernel(const float* __restrict__ x, const float* __restrict__ state)
{
    int idx = blockIdx.x * blockDim.x + threadIdx.x;
    if (idx >= Nn * BC) return;
    int m = idx / BC;
    int j = idx - m * BC;
    int b = j / Cc;
    int c = j - b * Cc;
    float v;
    if (c < DIN) v = x[((size_t)b * Nn + m) * DIN + c];
    else         v = state[((size_t)b * Nn + m) * Hh + (c - DIN)];
    g_Xt[idx] = v;
    __nv_bfloat16 h, l;
    split_bf16(v, h, l);
    g_Xh[idx] = h;
    g_Xl[idx] = l;
}

__global__ void build_ct_kernel(const float* __restrict__ x, const float* __restrict__ state)
{
    int idx = blockIdx.x * blockDim.x + threadIdx.x;
    if (idx >= Nn * BC) return;
    int m = idx / BC;
    int j = idx - m * BC;
    int b = j / Cc;
    int c = j - b * Cc;
    float v;
    if (c < DIN) v = x[((size_t)b * Nn + m) * DIN + c];
    else {
        size_t o = ((size_t)b * Nn + m) * Hh + (c - DIN);
        v = g_z[o] * state[o];
    }
    g_Ct[idx] = v;
    __nv_bfloat16 h, l;
    split_bf16(v, h, l);
    g_Xh[idx] = h;   // reuse: z/r GEMMs already consumed the xs version
    g_Xl[idx] = l;
}

// ---------------- 4) Wn_all[g][n][j] = sum_d e[g][n][d] * W_pool[d][j] ----------------
__global__ __launch_bounds__(256) void wn_kernel(const float* __restrict__ Wz,
                                                 const float* __restrict__ Wr,
                                                 const float* __restrict__ Wu)
{
    int gate = blockIdx.z;
    const float* Wp = (gate == 0) ? Wz : (gate == 1) ? Wr : Wu;
    int j0 = blockIdx.x * 128;
    int n0 = blockIdx.y * 128;
    __shared__ __align__(16) float sE[128][Dd];
    __shared__ __align__(16) float sW[Dd][128];
    int t = threadIdx.x;

    #pragma unroll
    for (int q = 0; q < 2; q++) {
        int id  = q * 256 + t;
        int rr  = id >> 2, c4 = id & 3;
        *(float4*)&sE[rr][c4 * 4] = *(const float4*)&g_e[gate][(n0 + rr) * Dd + c4 * 4];
        int wr  = id >> 5, wc4 = id & 31;
        *(float4*)&sW[wr][wc4 * 4] = *(const float4*)&Wp[(size_t)wr * WSZ + j0 + wc4 * 4];
    }
    __syncthreads();

    int jl  = (t & 31) * 4;
    int nl0 = (t >> 5) * 16;
    float acc[16][4] = {};
    #pragma unroll
    for (int d = 0; d < Dd; d++) {
        float4 wv = *(float4*)&sW[d][jl];
        #pragma unroll
        for (int r = 0; r < 16; r++) {
            float ev = sE[nl0 + r][d];
            acc[r][0] += ev * wv.x;
            acc[r][1] += ev * wv.y;
            acc[r][2] += ev * wv.z;
            acc[r][3] += ev * wv.w;
        }
    }
    #pragma unroll
    for (int r = 0; r < 16; r++) {
        float4 v = make_float4(acc[r][0], acc[r][1], acc[r][2], acc[r][3]);
        *(float4*)&g_Wn[gate][(size_t)(n0 + nl0 + r) * WSZ + j0 + jl] = v;
    }
}

// ---------------- 5) tensor-core GEMM: G = A @ X  via bf16 hi/lo split -------------
// G ≈ Ah*Xh + Ah*Xl + Al*Xh  (fp32 accum; missing lo*lo term ~2^-18 rel)
// Block 128x128, K-step 16, 8 warps (2x4), warp tile 64x32, mma m16n8k16.
// grid: (33, 16, nz)
#define KT (Nn / 16)         // 128
#define SA_STRIDE 24         // 16 k + 8 pad (48B rows: LDSM conflict-free)
#define SX_STRIDE 136        // 128 n + 8 pad (272B rows: LDSM conflict-free)
__global__ __launch_bounds__(256, 2) void sgemm_tc_kernel(int gateOff, int outOff)
{
    const __nv_bfloat16* Ah = g_Ah[gateOff + blockIdx.z];
    const __nv_bfloat16* Al = g_Al[gateOff + blockIdx.z];
    float* G = g_G[outOff + blockIdx.z];

    int j0 = blockIdx.x * 128;
    int r0 = blockIdx.y * 128;

    __shared__ __align__(16) __nv_bfloat16 sA[2][2][128 * SA_STRIDE];  // [buf][hi/lo] 24576B
    __shared__ __align__(16) __nv_bfloat16 sX[2][2][16 * SX_STRIDE];   // [buf][hi/lo] 17408B

    int t    = threadIdx.x;
    int lane = t & 31;
    int wid  = t >> 5;
    int warp_m = (wid >> 2) * 64;   // 0 or 64
    int warp_n = (wid & 3) * 32;    // 0,32,64,96

    float c[4][4][4] = {};          // [mi][nj][frag]

    // per-thread tile-load coordinates (16B each)
    int am = t >> 1,  ak = (t & 1) * 8;     // A: 128 rows x 16 k
    int xk = t >> 4,  xn = (t & 15) * 8;    // X: 16 k x 128 n

    const __nv_bfloat16* gAh = Ah + (size_t)(r0 + am) * Nn + ak;
    const __nv_bfloat16* gAl = Al + (size_t)(r0 + am) * Nn + ak;
    const __nv_bfloat16* gXh = g_Xh + (size_t)xk * BC + j0 + xn;
    const __nv_bfloat16* gXl = g_Xl + (size_t)xk * BC + j0 + xn;

    uint32_t aBase = (uint32_t)__cvta_generic_to_shared(&sA[0][0][0]);
    uint32_t xBase = (uint32_t)__cvta_generic_to_shared(&sX[0][0][0]);
    uint32_t dstA  = (uint32_t)(am * SA_STRIDE + ak) * 2;
    uint32_t dstX  = (uint32_t)(xk * SX_STRIDE + xn) * 2;

    // ldmatrix lane offsets
    uint32_t aLM = (uint32_t)(((lane & 15) * SA_STRIDE + (lane >> 4) * 8) * 2);
    uint32_t xLM = (uint32_t)(((lane & 15) * SX_STRIDE + warp_n + (lane >> 4) * 8) * 2);

    const uint32_t A_BUF = 2u * 128 * SA_STRIDE * 2;  // bytes per buf (both splits)
    const uint32_t A_SPL = 128u * SA_STRIDE * 2;
    const uint32_t X_BUF = 2u * 16 * SX_STRIDE * 2;
    const uint32_t X_SPL = 16u * SX_STRIDE * 2;

    // prologue: kt = 0 into buf 0
    CP_ASYNC16(aBase + dstA,         gAh);
    CP_ASYNC16(aBase + A_SPL + dstA, gAl);
    CP_ASYNC16(xBase + dstX,         gXh);
    CP_ASYNC16(xBase + X_SPL + dstX, gXl);
    CP_COMMIT();
    CP_WAIT0();
    __syncthreads();

    for (int kt = 0; kt < KT; kt++) {
        int cur = kt & 1, nxt = cur ^ 1;
        if (kt + 1 < KT) {
            int k0n = (kt + 1) * 16;
            CP_ASYNC16(aBase + nxt * A_BUF + dstA,         gAh + k0n);
            CP_ASYNC16(aBase + nxt * A_BUF + A_SPL + dstA, gAl + k0n);
            CP_ASYNC16(xBase + nxt * X_BUF + dstX,         gXh + (size_t)k0n * BC);
            CP_ASYNC16(xBase + nxt * X_BUF + X_SPL + dstX, gXl + (size_t)k0n * BC);
            CP_COMMIT();
        }

        // B fragments: 2 n16-pairs x {hi,lo}
        uint32_t bh[2][4], bl[2][4];
        #pragma unroll
        for (int njp = 0; njp < 2; njp++) {
            uint32_t xa = xBase + cur * X_BUF + njp * 32 + xLM;
            LDSM_X4_T(bh[njp], xa);
            LDSM_X4_T(bl[njp], xa + X_SPL);
        }

        #pragma unroll
        for (int mi = 0; mi < 4; mi++) {
            uint32_t ah[4], al[4];
            uint32_t aa = aBase + cur * A_BUF + (uint32_t)((warp_m + mi * 16) * SA_STRIDE * 2) + aLM;
            LDSM_X4(ah, aa);
            LDSM_X4(al, aa + A_SPL);
            #pragma unroll
            for (int nj = 0; nj < 4; nj++) {
                uint32_t* bhp = &bh[nj >> 1][(nj & 1) * 2];
                uint32_t* blp = &bl[nj >> 1][(nj & 1) * 2];
                MMA_BF16(c[mi][nj], ah, bhp[0], bhp[1]);   // Ah*Xh
                MMA_BF16(c[mi][nj], ah, blp[0], blp[1]);   // Ah*Xl
                MMA_BF16(c[mi][nj], al, bhp[0], bhp[1]);   // Al*Xh
            }
        }
        CP_WAIT0();
        __syncthreads();
    }

    // epilogue: c frag layout — c0,c1: row=lane>>2, cols (lane&3)*2,+1; c2,c3: row+8
    #pragma unroll
    for (int mi = 0; mi < 4; mi++) {
        #pragma unroll
        for (int nj = 0; nj < 4; nj++) {
            int row = r0 + warp_m + mi * 16 + (lane >> 2);
            int col = j0 + warp_n + nj * 8 + (lane & 3) * 2;
            *(float2*)&G[(size_t)row * BC + col]       = make_float2(c[mi][nj][0], c[mi][nj][1]);
            *(float2*)&G[(size_t)(row + 8) * BC + col] = make_float2(c[mi][nj][2], c[mi][nj][3]);
        }
    }
}

// ---------------- 6) per-node combine + activation (+ final GRU fuse for gate u) ----------
__global__ __launch_bounds__(256) void combine_kernel(const float* __restrict__ b_pool,
                                                      const float* __restrict__ state,
                                                      float* __restrict__ dout,
                                                      int gate, int useCt, int gsel, int outMode)
{
    __shared__ __align__(16) float sW[Cc * Oo];
    __shared__ __align__(16) float sXT[Cc][68];
    __shared__ float sBias[Oo];
    __shared__ float se[Dd];

    int n = blockIdx.x, t = threadIdx.x;
    if (t < Dd) se[t] = g_e[gate][n * Dd + t];
    __syncthreads();
    if (t < Oo) {
        float a = 0.f;
        #pragma unroll
        for (int d = 0; d < Dd; d++) a += se[d] * b_pool[d * Oo + t];
        sBias[t] = a;
    }

    int tx = t & 15, ty = t >> 4;
    float acc[4][4] = {};
    const float* Wn = &g_Wn[gate][(size_t)n * WSZ];

    #pragma unroll
    for (int pass = 0; pass < 2; pass++) {
        const float* xs = pass ? &g_G[gsel][(size_t)n * BC]
                               : (useCt ? &g_Ct[(size_t)n * BC] : &g_Xt[(size_t)n * BC]);
        const float4* wsrc = (const float4*)(Wn + pass * (Cc * Oo));
        for (int i4 = t; i4 < (Cc * Oo) / 4; i4 += 256)
            ((float4*)sW)[i4] = wsrc[i4];
        for (int idx = t; idx < BC; idx += 256) {
            int b = idx / Cc, c = idx - b * Cc;
            sXT[c][b] = xs[idx];
        }
        __syncthreads();
        #pragma unroll
        for (int k = 0; k < Cc; k++) {
            float4 bv = *(float4*)&sW[k * Oo + tx * 4];
            float4 av = *(float4*)&sXT[k][ty * 4];
            float aa[4] = {av.x, av.y, av.z, av.w};
            float bb[4] = {bv.x, bv.y, bv.z, bv.w};
            #pragma unroll
            for (int i = 0; i < 4; i++)
                #pragma unroll
                for (int j = 0; j < 4; j++)
                    acc[i][j] += aa[i] * bb[j];
        }
        __syncthreads();
    }

    #pragma unroll
    for (int bi = 0; bi < 4; bi++) {
        int b = ty * 4 + bi;
        size_t base = ((size_t)b * Nn + n) * Hh + tx * 4;
        float4 v;
        if (outMode == 2) {
            float4 rv = *(const float4*)&g_r[base];
            float4 sv = *(const float4*)&state[base];
            float h0 = fast_tanh(acc[bi][0] + sBias[tx * 4 + 0]);
            float h1 = fast_tanh(acc[bi][1] + sBias[tx * 4 + 1]);
            float h2 = fast_tanh(acc[bi][2] + sBias[tx * 4 + 2]);
            float h3 = fast_tanh(acc[bi][3] + sBias[tx * 4 + 3]);
            v.x = rv.x * sv.x + (1.f - rv.x) * h0;
            v.y = rv.y * sv.y + (1.f - rv.y) * h1;
            v.z = rv.z * sv.z + (1.f - rv.z) * h2;
            v.w = rv.w * sv.w + (1.f - rv.w) * h3;
            *(float4*)&dout[base] = v;
        } else {
            v.x = fast_sigmoid(acc[bi][0] + sBias[tx * 4 + 0]);
            v.y = fast_sigmoid(acc[bi][1] + sBias[tx * 4 + 1]);
            v.z = fast_sigmoid(acc[bi][2] + sBias[tx * 4 + 2]);
            v.w = fast_sigmoid(acc[bi][3] + sBias[tx * 4 + 3]);
            float* outp = (outMode == 0) ? g_z : g_r;
            *(float4*)&outp[base] = v;
        }
    }
}

// ---------------- launcher ----------------
extern "C" void kernel_launch(void* const* d_in, const int* in_sizes, int n_in,
                              void* d_out, int out_size)
{
    (void)in_sizes; (void)n_in; (void)out_size;
    const float* x   = (const float*)d_in[0];
    const float* st  = (const float*)d_in[1];
    const float* ne  = (const float*)d_in[2];
    const float* te  = (const float*)d_in[3];
    const float* Wz  = (const float*)d_in[4];
    const float* bz  = (const float*)d_in[5];
    const float* gz  = (const float*)d_in[6];
    const float* bez = (const float*)d_in[7];
    const float* Wr  = (const float*)d_in[8];
    const float* brr = (const float*)d_in[9];
    const float* gr  = (const float*)d_in[10];
    const float* ber = (const float*)d_in[11];
    const float* Wu  = (const float*)d_in[12];
    const float* bu  = (const float*)d_in[13];
    const float* gu  = (const float*)d_in[14];
    const float* beu = (const float*)d_in[15];
    float* out = (float*)d_out;

    compute_e_kernel<<<(3 * Nn + 255) / 256, 256>>>(ne, te, gz, bez, gr, ber, gu, beu);
    softmax_kernel<<<dim3(Nn / 4, 3), 256>>>();
    build_xt_kernel<<<(Nn * BC + 255) / 256, 256>>>(x, st);
    wn_kernel<<<dim3(WSZ / 128, Nn / 128, 3), 256>>>(Wz, Wr, Wu);

    // z and r big GEMMs batched (z in gridDim.z), tensor cores
    sgemm_tc_kernel<<<dim3(BC / 128, Nn / 128, 2), 256>>>(0, 0);
    combine_kernel<<<Nn, 256>>>(bz, st, out, 0, 0, 0, 0);   // -> g_z
    combine_kernel<<<Nn, 256>>>(brr, st, out, 1, 0, 1, 1);  // -> g_r

    build_ct_kernel<<<(Nn * BC + 255) / 256, 256>>>(x, st); // cand = [x, z*state] (+ bf16 hi/lo)
    sgemm_tc_kernel<<<dim3(BC / 128, Nn / 128, 1), 256>>>(2, 0);
    combine_kernel<<<Nn, 256>>>(bu, st, out, 2, 1, 0, 2);   // -> d_out (GRU fuse)
}

// round 16
// speedup vs baseline: 2.4718x; 1.2142x over previous
#include <cuda_runtime.h>
#include <cuda_fp16.h>
#include <math.h>
#include <stdint.h>

// Problem dims (fixed by the dataset)
#define Bq   64
#define Nn   2048
#define DIN  2
#define Hh   64
#define Dd   16
#define Cc   66
#define Oo   64
#define BC   4224    // Bq*Cc
#define WSZ  8448    // 2*Cc*Oo

// ---------------- scratch (device globals; no allocations) ----------------
__device__ float g_e [3][Nn * Dd];
__device__ __align__(256) __half g_Af[3][Nn * Nn];   // adjacency, single fp16, [n][m] K-major
__device__ __align__(256) float g_Xt[Nn * BC];       // X  [m][j] fp32 (combine pass0)
__device__ __align__(256) float g_Ct[Nn * BC];       // cand [m][j] fp32
__device__ __align__(256) __half g_Xh[Nn * BC];      // X hi (fp16) [k][j]  — reused for cand
__device__ __align__(256) __half g_Xl[Nn * BC];      // X lo (fp16 residual)
__device__ __align__(256) float g_G [2][Nn * BC];    // A @ X results (fp32)
__device__ __align__(256) float g_Wn[3][Nn * WSZ];
__device__ float g_z [Bq * Nn * Hh];
__device__ float g_r [Bq * Nn * Hh];

// ---------------- PTX helpers ----------------
#define LDSM_X4(d, addr) \
    asm volatile("ldmatrix.sync.aligned.m8n8.x4.shared.b16 {%0,%1,%2,%3}, [%4];" \
        : "=r"(d[0]), "=r"(d[1]), "=r"(d[2]), "=r"(d[3]) : "r"(addr))
#define LDSM_X4_T(d, addr) \
    asm volatile("ldmatrix.sync.aligned.m8n8.x4.trans.shared.b16 {%0,%1,%2,%3}, [%4];" \
        : "=r"(d[0]), "=r"(d[1]), "=r"(d[2]), "=r"(d[3]) : "r"(addr))
#define MMA_F16(c, a, b0, b1) \
    asm volatile("mma.sync.aligned.m16n8k16.row.col.f32.f16.f16.f32 " \
        "{%0,%1,%2,%3}, {%4,%5,%6,%7}, {%8,%9}, {%0,%1,%2,%3};" \
        : "+f"(c[0]), "+f"(c[1]), "+f"(c[2]), "+f"(c[3]) \
        : "r"(a[0]), "r"(a[1]), "r"(a[2]), "r"(a[3]), "r"(b0), "r"(b1))
#define CP_ASYNC16(smem_u32, gptr) \
    asm volatile("cp.async.cg.shared.global [%0], [%1], 16;" :: "r"(smem_u32), "l"(gptr))
#define CP_COMMIT() asm volatile("cp.async.commit_group;" ::: "memory")
#define CP_WAIT0()  asm volatile("cp.async.wait_group 0;" ::: "memory")

__device__ __forceinline__ void split_f16(float v, __half& h, __half& l)
{
    h = __float2half(v);
    l = __float2half(v - __half2float(h));
}

// FFMA-only exp (no MUFU)
__device__ __forceinline__ float fast_exp(float x)
{
    float y = x * 1.442695041f;
    y = fminf(fmaxf(y, -125.0f), 125.0f);
    int   ni = __float2int_rn(y);
    float f  = y - (float)ni;
    float p = 1.339077600e-3f;
    p = fmaf(p, f, 9.618012930e-3f);
    p = fmaf(p, f, 5.550487860e-2f);
    p = fmaf(p, f, 2.402264923e-1f);
    p = fmaf(p, f, 6.931471825e-1f);
    p = fmaf(p, f, 1.0f);
    float s = __int_as_float((ni + 127) << 23);
    return p * s;
}
__device__ __forceinline__ float fast_sigmoid(float x) { return 1.0f / (1.0f + fast_exp(-x)); }
__device__ __forceinline__ float fast_tanh(float x)
{
    float xc = fminf(fmaxf(x, -15.0f), 15.0f);
    return 1.0f - 2.0f / (fast_exp(2.0f * xc) + 1.0f);
}

// ---------------- 1) layernorm embeddings ----------------
__global__ void compute_e_kernel(const float* __restrict__ ne, const float* __restrict__ te,
                                 const float* __restrict__ gz, const float* __restrict__ bz,
                                 const float* __restrict__ gr, const float* __restrict__ br,
                                 const float* __restrict__ gu, const float* __restrict__ bu)
{
    int idx = blockIdx.x * blockDim.x + threadIdx.x;
    if (idx >= 3 * Nn) return;
    int g = idx / Nn, n = idx - g * Nn;
    const float* ga = (g == 0) ? gz : (g == 1) ? gr : gu;
    const float* be = (g == 0) ? bz : (g == 1) ? br : bu;

    float v[Dd];
    float m = 0.f;
    #pragma unroll
    for (int d = 0; d < Dd; d++) { v[d] = ne[n * Dd + d] + te[d]; m += v[d]; }
    m *= (1.f / Dd);
    float var = 0.f;
    #pragma unroll
    for (int d = 0; d < Dd; d++) { float t = v[d] - m; var += t * t; }
    var *= (1.f / Dd);
    float rs = rsqrtf(var + 1e-12f);
    #pragma unroll
    for (int d = 0; d < Dd; d++)
        g_e[g][n * Dd + d] = (v[d] - m) * rs * ga[d] + be[d];
}

// ---------------- 2) A = softmax(e e^T); writes single fp16 ----------------
__global__ __launch_bounds__(256) void softmax_kernel()
{
    int g  = blockIdx.y;
    int n0 = blockIdx.x * 4;
    __shared__ float rows[4][Nn];
    __shared__ float en[4][Dd];
    __shared__ float red[4][8];
    int t = threadIdx.x;

    if (t < 64) en[t >> 4][t & 15] = g_e[g][(n0 + (t >> 4)) * Dd + (t & 15)];
    __syncthreads();

    float lmax[4] = {-1e30f, -1e30f, -1e30f, -1e30f};
    for (int m = t; m < Nn; m += 256) {
        float ev[Dd];
        #pragma unroll
        for (int d = 0; d < Dd; d++) ev[d] = g_e[g][m * Dd + d];
        #pragma unroll
        for (int r = 0; r < 4; r++) {
            float s = 0.f;
            #pragma unroll
            for (int d = 0; d < Dd; d++) s += ev[d] * en[r][d];
            rows[r][m] = s;
            lmax[r] = fmaxf(lmax[r], s);
        }
    }
    #pragma unroll
    for (int r = 0; r < 4; r++) {
        float v = lmax[r];
        #pragma unroll
        for (int off = 16; off; off >>= 1) v = fmaxf(v, __shfl_xor_sync(0xffffffffu, v, off));
        if ((t & 31) == 0) red[r][t >> 5] = v;
    }
    __syncthreads();
    float bmax[4];
    #pragma unroll
    for (int r = 0; r < 4; r++) {
        float v = red[r][0];
        #pragma unroll
        for (int w = 1; w < 8; w++) v = fmaxf(v, red[r][w]);
        bmax[r] = v;
    }
    __syncthreads();

    float lsum[4] = {0.f, 0.f, 0.f, 0.f};
    for (int m = t; m < Nn; m += 256) {
        #pragma unroll
        for (int r = 0; r < 4; r++) {
            float ev = fast_exp(rows[r][m] - bmax[r]);
            rows[r][m] = ev;
            lsum[r] += ev;
        }
    }
    #pragma unroll
    for (int r = 0; r < 4; r++) {
        float v = lsum[r];
        #pragma unroll
        for (int off = 16; off; off >>= 1) v += __shfl_xor_sync(0xffffffffu, v, off);
        if ((t & 31) == 0) red[r][t >> 5] = v;
    }
    __syncthreads();
    float inv[4];
    #pragma unroll
    for (int r = 0; r < 4; r++) {
        float v = 0.f;
        #pragma unroll
        for (int w = 0; w < 8; w++) v += red[r][w];
        inv[r] = 1.f / v;
    }
    for (int m = t; m < Nn; m += 256) {
        #pragma unroll
        for (int r = 0; r < 4; r++) {
            float v = rows[r][m] * inv[r];
            g_Af[g][(size_t)(n0 + r) * Nn + m] = __float2half(v);
        }
    }
}

// ---------------- 3) transposes: fp32 + fp16 hi/lo ----------------
__global__ void build_xt_kernel(const float* __restrict__ x, const float* __restrict__ state)
{
    int idx = blockIdx.x * blockDim.x + threadIdx.x;
    if (idx >= Nn * BC) return;
    int m = idx / BC;
    int j = idx - m * BC;
    int b = j / Cc;
    int c = j - b * Cc;
    float v;
    if (c < DIN) v = x[((size_t)b * Nn + m) * DIN + c];
    else         v = state[((size_t)b * Nn + m) * Hh + (c - DIN)];
    g_Xt[idx] = v;
    __half h, l;
    split_f16(v, h, l);
    g_Xh[idx] = h;
    g_Xl[idx] = l;
}

__global__ void build_ct_kernel(const float* __restrict__ x, const float* __restrict__ state)
{
    int idx = blockIdx.x * blockDim.x + threadIdx.x;
    if (idx >= Nn * BC) return;
    int m = idx / BC;
    int j = idx - m * BC;
    int b = j / Cc;
    int c = j - b * Cc;
    float v;
    if (c < DIN) v = x[((size_t)b * Nn + m) * DIN + c];
    else {
        size_t o = ((size_t)b * Nn + m) * Hh + (c - DIN);
        v = g_z[o] * state[o];
    }
    g_Ct[idx] = v;
    __half h, l;
    split_f16(v, h, l);
    g_Xh[idx] = h;   // reuse: z/r GEMMs already consumed the xs version
    g_Xl[idx] = l;
}

// ---------------- 4) Wn_all[g][n][j] = sum_d e[g][n][d] * W_pool[d][j] ----------------
__global__ __launch_bounds__(256) void wn_kernel(const float* __restrict__ Wz,
                                                 const float* __restrict__ Wr,
                                                 const float* __restrict__ Wu)
{
    int gate = blockIdx.z;
    const float* Wp = (gate == 0) ? Wz : (gate == 1) ? Wr : Wu;
    int j0 = blockIdx.x * 128;
    int n0 = blockIdx.y * 128;
    __shared__ __align__(16) float sE[128][Dd];
    __shared__ __align__(16) float sW[Dd][128];
    int t = threadIdx.x;

    #pragma unroll
    for (int q = 0; q < 2; q++) {
        int id  = q * 256 + t;
        int rr  = id >> 2, c4 = id & 3;
        *(float4*)&sE[rr][c4 * 4] = *(const float4*)&g_e[gate][(n0 + rr) * Dd + c4 * 4];
        int wr  = id >> 5, wc4 = id & 31;
        *(float4*)&sW[wr][wc4 * 4] = *(const float4*)&Wp[(size_t)wr * WSZ + j0 + wc4 * 4];
    }
    __syncthreads();

    int jl  = (t & 31) * 4;
    int nl0 = (t >> 5) * 16;
    float acc[16][4] = {};
    #pragma unroll
    for (int d = 0; d < Dd; d++) {
        float4 wv = *(float4*)&sW[d][jl];
        #pragma unroll
        for (int r = 0; r < 16; r++) {
            float ev = sE[nl0 + r][d];
            acc[r][0] += ev * wv.x;
            acc[r][1] += ev * wv.y;
            acc[r][2] += ev * wv.z;
            acc[r][3] += ev * wv.w;
        }
    }
    #pragma unroll
    for (int r = 0; r < 16; r++) {
        float4 v = make_float4(acc[r][0], acc[r][1], acc[r][2], acc[r][3]);
        *(float4*)&g_Wn[gate][(size_t)(n0 + nl0 + r) * WSZ + j0 + jl] = v;
    }
}

// ---------------- 5) tensor-core GEMM: G = A @ X via fp16 2-term -------------
// G = A*Xh + A*Xl (A single fp16; X split hi/lo fp16; fp32 accum).
// Block 128x128, K-step 16, 8 warps (2x4), warp tile 64x32, mma m16n8k16.
#define KT (Nn / 16)         // 128
#define SA_STRIDE 24         // 16 k + 8 pad
#define SX_STRIDE 136        // 128 n + 8 pad
__global__ __launch_bounds__(256, 2) void sgemm_tc_kernel(int gateOff, int outOff)
{
    const __half* Af = g_Af[gateOff + blockIdx.z];
    float* G = g_G[outOff + blockIdx.z];

    int j0 = blockIdx.x * 128;
    int r0 = blockIdx.y * 128;

    __shared__ __align__(16) __half sA[2][128 * SA_STRIDE];      // 2 x 6144 B
    __shared__ __align__(16) __half sX[2][2][16 * SX_STRIDE];    // 2 buf x {hi,lo} x 4352 B

    int t    = threadIdx.x;
    int lane = t & 31;
    int wid  = t >> 5;
    int warp_m = (wid >> 2) * 64;   // 0 or 64
    int warp_n = (wid & 3) * 32;    // 0,32,64,96

    float c[4][4][4] = {};          // [mi][nj][frag]

    int am = t >> 1,  ak = (t & 1) * 8;     // A: 128 rows x 16 k
    int xk = t >> 4,  xn = (t & 15) * 8;    // X: 16 k x 128 n

    const __half* gA  = Af   + (size_t)(r0 + am) * Nn + ak;
    const __half* gXh = g_Xh + (size_t)xk * BC + j0 + xn;
    const __half* gXl = g_Xl + (size_t)xk * BC + j0 + xn;

    uint32_t aBase = (uint32_t)__cvta_generic_to_shared(&sA[0][0]);
    uint32_t xBase = (uint32_t)__cvta_generic_to_shared(&sX[0][0][0]);
    uint32_t dstA  = (uint32_t)(am * SA_STRIDE + ak) * 2;
    uint32_t dstX  = (uint32_t)(xk * SX_STRIDE + xn) * 2;

    uint32_t aLM = (uint32_t)(((lane & 15) * SA_STRIDE + (lane >> 4) * 8) * 2);
    uint32_t xLM = (uint32_t)(((lane & 15) * SX_STRIDE + warp_n + (lane >> 4) * 8) * 2);

    const uint32_t A_BUF = 128u * SA_STRIDE * 2;      // 6144
    const uint32_t X_BUF = 2u * 16 * SX_STRIDE * 2;   // 8704
    const uint32_t X_SPL = 16u * SX_STRIDE * 2;       // 4352

    // prologue: kt = 0 into buf 0
    CP_ASYNC16(aBase + dstA, gA);
    CP_ASYNC16(xBase + dstX,         gXh);
    CP_ASYNC16(xBase + X_SPL + dstX, gXl);
    CP_COMMIT();
    CP_WAIT0();
    __syncthreads();

    for (int kt = 0; kt < KT; kt++) {
        int cur = kt & 1, nxt = cur ^ 1;
        if (kt + 1 < KT) {
            int k0n = (kt + 1) * 16;
            CP_ASYNC16(aBase + nxt * A_BUF + dstA, gA + k0n);
            CP_ASYNC16(xBase + nxt * X_BUF + dstX,         gXh + (size_t)k0n * BC);
            CP_ASYNC16(xBase + nxt * X_BUF + X_SPL + dstX, gXl + (size_t)k0n * BC);
            CP_COMMIT();
        }

        // B fragments: 2 n16-pairs x {hi,lo}
        uint32_t bh[2][4], bl[2][4];
        #pragma unroll
        for (int njp = 0; njp < 2; njp++) {
            uint32_t xa = xBase + cur * X_BUF + njp * 32 + xLM;
            LDSM_X4_T(bh[njp], xa);
            LDSM_X4_T(bl[njp], xa + X_SPL);
        }

        #pragma unroll
        for (int mi = 0; mi < 4; mi++) {
            uint32_t af[4];
            uint32_t aa = aBase + cur * A_BUF + (uint32_t)((warp_m + mi * 16) * SA_STRIDE * 2) + aLM;
            LDSM_X4(af, aa);
            #pragma unroll
            for (int nj = 0; nj < 4; nj++) {
                uint32_t* bhp = &bh[nj >> 1][(nj & 1) * 2];
                uint32_t* blp = &bl[nj >> 1][(nj & 1) * 2];
                MMA_F16(c[mi][nj], af, bhp[0], bhp[1]);   // A*Xh
                MMA_F16(c[mi][nj], af, blp[0], blp[1]);   // A*Xl
            }
        }
        CP_WAIT0();
        __syncthreads();
    }

    // epilogue: c frag layout — c0,c1: row=lane>>2, cols (lane&3)*2,+1; c2,c3: row+8
    #pragma unroll
    for (int mi = 0; mi < 4; mi++) {
        #pragma unroll
        for (int nj = 0; nj < 4; nj++) {
            int row = r0 + warp_m + mi * 16 + (lane >> 2);
            int col = j0 + warp_n + nj * 8 + (lane & 3) * 2;
            *(float2*)&G[(size_t)row * BC + col]       = make_float2(c[mi][nj][0], c[mi][nj][1]);
            *(float2*)&G[(size_t)(row + 8) * BC + col] = make_float2(c[mi][nj][2], c[mi][nj][3]);
        }
    }
}

// ---------------- 6) per-node combine + activation (+ final GRU fuse for gate u) ----------
__global__ __launch_bounds__(256) void combine_kernel(const float* __restrict__ b_pool,
                                                      const float* __restrict__ state,
                                                      float* __restrict__ dout,
                                                      int gate, int useCt, int gsel, int outMode)
{
    __shared__ __align__(16) float sW[Cc * Oo];
    __shared__ __align__(16) float sXT[Cc][68];
    __shared__ float sBias[Oo];
    __shared__ float se[Dd];

    int n = blockIdx.x, t = threadIdx.x;
    if (t < Dd) se[t] = g_e[gate][n * Dd + t];
    __syncthreads();
    if (t < Oo) {
        float a = 0.f;
        #pragma unroll
        for (int d = 0; d < Dd; d++) a += se[d] * b_pool[d * Oo + t];
        sBias[t] = a;
    }

    int tx = t & 15, ty = t >> 4;
    float acc[4][4] = {};
    const float* Wn = &g_Wn[gate][(size_t)n * WSZ];

    #pragma unroll
    for (int pass = 0; pass < 2; pass++) {
        const float* xs = pass ? &g_G[gsel][(size_t)n * BC]
                               : (useCt ? &g_Ct[(size_t)n * BC] : &g_Xt[(size_t)n * BC]);
        const float4* wsrc = (const float4*)(Wn + pass * (Cc * Oo));
        for (int i4 = t; i4 < (Cc * Oo) / 4; i4 += 256)
            ((float4*)sW)[i4] = wsrc[i4];
        for (int idx = t; idx < BC; idx += 256) {
            int b = idx / Cc, c = idx - b * Cc;
            sXT[c][b] = xs[idx];
        }
        __syncthreads();
        #pragma unroll
        for (int k = 0; k < Cc; k++) {
            float4 bv = *(float4*)&sW[k * Oo + tx * 4];
            float4 av = *(float4*)&sXT[k][ty * 4];
            float aa[4] = {av.x, av.y, av.z, av.w};
            float bb[4] = {bv.x, bv.y, bv.z, bv.w};
            #pragma unroll
            for (int i = 0; i < 4; i++)
                #pragma unroll
                for (int j = 0; j < 4; j++)
                    acc[i][j] += aa[i] * bb[j];
        }
        __syncthreads();
    }

    #pragma unroll
    for (int bi = 0; bi < 4; bi++) {
        int b = ty * 4 + bi;
        size_t base = ((size_t)b * Nn + n) * Hh + tx * 4;
        float4 v;
        if (outMode == 2) {
            float4 rv = *(const float4*)&g_r[base];
            float4 sv = *(const float4*)&state[base];
            float h0 = fast_tanh(acc[bi][0] + sBias[tx * 4 + 0]);
            float h1 = fast_tanh(acc[bi][1] + sBias[tx * 4 + 1]);
            float h2 = fast_tanh(acc[bi][2] + sBias[tx * 4 + 2]);
            float h3 = fast_tanh(acc[bi][3] + sBias[tx * 4 + 3]);
            v.x = rv.x * sv.x + (1.f - rv.x) * h0;
            v.y = rv.y * sv.y + (1.f - rv.y) * h1;
            v.z = rv.z * sv.z + (1.f - rv.z) * h2;
            v.w = rv.w * sv.w + (1.f - rv.w) * h3;
            *(float4*)&dout[base] = v;
        } else {
            v.x = fast_sigmoid(acc[bi][0] + sBias[tx * 4 + 0]);
            v.y = fast_sigmoid(acc[bi][1] + sBias[tx * 4 + 1]);
            v.z = fast_sigmoid(acc[bi][2] + sBias[tx * 4 + 2]);
            v.w = fast_sigmoid(acc[bi][3] + sBias[tx * 4 + 3]);
            float* outp = (outMode == 0) ? g_z : g_r;
            *(float4*)&outp[base] = v;
        }
    }
}

// ---------------- launcher ----------------
extern "C" void kernel_launch(void* const* d_in, const int* in_sizes, int n_in,
                              void* d_out, int out_size)
{
    (void)in_sizes; (void)n_in; (void)out_size;
    const float* x   = (const float*)d_in[0];
    const float* st  = (const float*)d_in[1];
    const float* ne  = (const float*)d_in[2];
    const float* te  = (const float*)d_in[3];
    const float* Wz  = (const float*)d_in[4];
    const float* bz  = (const float*)d_in[5];
    const float* gz  = (const float*)d_in[6];
    const float* bez = (const float*)d_in[7];
    const float* Wr  = (const float*)d_in[8];
    const float* brr = (const float*)d_in[9];
    const float* gr  = (const float*)d_in[10];
    const float* ber = (const float*)d_in[11];
    const float* Wu  = (const float*)d_in[12];
    const float* bu  = (const float*)d_in[13];
    const float* gu  = (const float*)d_in[14];
    const float* beu = (const float*)d_in[15];
    float* out = (float*)d_out;

    compute_e_kernel<<<(3 * Nn + 255) / 256, 256>>>(ne, te, gz, bez, gr, ber, gu, beu);
    softmax_kernel<<<dim3(Nn / 4, 3), 256>>>();
    build_xt_kernel<<<(Nn * BC + 255) / 256, 256>>>(x, st);
    wn_kernel<<<dim3(WSZ / 128, Nn / 128, 3), 256>>>(Wz, Wr, Wu);

    // z and r big GEMMs batched (z in gridDim.z), tensor cores (mma.sync fp16)
    sgemm_tc_kernel<<<dim3(BC / 128, Nn / 128, 2), 256>>>(0, 0);
    combine_kernel<<<Nn, 256>>>(bz, st, out, 0, 0, 0, 0);   // -> g_z
    combine_kernel<<<Nn, 256>>>(brr, st, out, 1, 0, 1, 1);  // -> g_r

    build_ct_kernel<<<(Nn * BC + 255) / 256, 256>>>(x, st); // cand = [x, z*state] (+ fp16 hi/lo)
    sgemm_tc_kernel<<<dim3(BC / 128, Nn / 128, 1), 256>>>(2, 0);
    combine_kernel<<<Nn, 256>>>(bu, st, out, 2, 1, 0, 2);   // -> d_out (GRU fuse)
}